// round 2
// baseline (speedup 1.0000x reference)
#include <cuda_runtime.h>
#include <cuda_bf16.h>
#include <math.h>

#define BSZ 4
#define SEQ 1024
#define DM 1024
#define NH 16
#define HDIM 64
#define BH (BSZ*NH)            // 64
#define ROWS (BSZ*SEQ)         // 4096
#define CATW (NH*(HDIM+1))     // 1040
#define FF 4095
#define FFL 4096

// -------------------- scratch (static device allocations) --------------------
__device__ float g_lx [ROWS*DM];
__device__ float g_tmp[ROWS*DM];
__device__ float g_q  [BH*SEQ*65];
__device__ float g_k  [BH*SEQ*65];
__device__ float g_v  [BH*SEQ*65];
__device__ float g_sc [(size_t)BH*SEQ*SEQ];       // 256 MB
__device__ float g_mid[BH*SEQ*65];
__device__ float g_cat[ROWS*CATW];
__device__ float g_ax [ROWS*DM];
__device__ float g_x1 [ROWS*DM];
__device__ float g_h  [ROWS*DM];
__device__ float g_hfc[(size_t)ROWS*FF];
__device__ float g_hg [(size_t)ROWS*FFL];
__device__ float g_hpj[ROWS*DM];

// -------------------- reductions --------------------
__device__ __forceinline__ float warpReduceSum(float v) {
    #pragma unroll
    for (int o = 16; o; o >>= 1) v += __shfl_xor_sync(0xffffffffu, v, o);
    return v;
}
__device__ __forceinline__ float warpReduceMax(float v) {
    #pragma unroll
    for (int o = 16; o; o >>= 1) v = fmaxf(v, __shfl_xor_sync(0xffffffffu, v, o));
    return v;
}
__device__ float blockReduceSum(float v) {
    __shared__ float sbuf[32];
    __shared__ float res;
    int lane = threadIdx.x & 31, wid = threadIdx.x >> 5;
    v = warpReduceSum(v);
    if (lane == 0) sbuf[wid] = v;
    __syncthreads();
    if (wid == 0) {
        float t = (lane < ((int)blockDim.x >> 5)) ? sbuf[lane] : 0.f;
        t = warpReduceSum(t);
        if (lane == 0) res = t;
    }
    __syncthreads();
    float r = res;
    __syncthreads();
    return r;
}
__device__ float blockReduceMax(float v) {
    __shared__ float sbuf[32];
    __shared__ float res;
    int lane = threadIdx.x & 31, wid = threadIdx.x >> 5;
    v = warpReduceMax(v);
    if (lane == 0) sbuf[wid] = v;
    __syncthreads();
    if (wid == 0) {
        float t = (lane < ((int)blockDim.x >> 5)) ? sbuf[lane] : -1e30f;
        t = warpReduceMax(t);
        if (lane == 0) res = t;
    }
    __syncthreads();
    float r = res;
    __syncthreads();
    return r;
}

// -------------------- Lorentz layernorm + lift --------------------
// in: row of DM floats (col0 = time, ignored). out: layernorm of space cols + new time.
__global__ void ln_lift_k(const float* __restrict__ x, const float* __restrict__ gamma,
                          const float* __restrict__ beta, float* __restrict__ out) {
    int row = blockIdx.x;
    const float* xs = x + (size_t)row * DM + 1;
    float* os = out + (size_t)row * DM;
    float s = 0.f;
    for (int i = threadIdx.x; i < DM - 1; i += blockDim.x) s += xs[i];
    s = blockReduceSum(s);
    float mu = s * (1.0f / (DM - 1));
    float v = 0.f;
    for (int i = threadIdx.x; i < DM - 1; i += blockDim.x) {
        float d = xs[i] - mu; v += d * d;
    }
    v = blockReduceSum(v);
    float rstd = rsqrtf(v * (1.0f / (DM - 1)) + 1e-5f);
    float sq = 0.f;
    for (int i = threadIdx.x; i < DM - 1; i += blockDim.x) {
        float y = (xs[i] - mu) * rstd * gamma[i] + beta[i];
        os[i + 1] = y;
        sq += y * y;
    }
    sq = blockReduceSum(sq);
    if (threadIdx.x == 0) os[0] = sqrtf(sq + 1.0f);
}

// -------------------- generic SGEMM 128x128x16, 8x8/thread --------------------
// C[m][n] = alpha * sum_k A[m][k]*B(k,n) + beta0 + bias[n]
// TRANS_B=false: B is K x N (ldb = row stride).  TRANS_B=true: B is N x K.
template <bool TRANS_B>
__global__ void sgemm_k(const float* __restrict__ A, const float* __restrict__ Bm,
                        const float* __restrict__ bias, float* __restrict__ C,
                        int M, int N, int K, int lda, int ldb, int ldc,
                        size_t sA, size_t sB, size_t sC, float alpha, float beta0) {
    __shared__ float As[16][132];
    __shared__ float Bs[16][132];
    A  += blockIdx.z * sA;
    Bm += blockIdx.z * sB;
    C  += blockIdx.z * sC;
    int rb = blockIdx.x * 128, cb = blockIdx.y * 128;
    int tid = threadIdx.x;
    int tx = tid & 15, ty = tid >> 4;
    float acc[8][8] = {};
    int nkt = (K + 15) >> 4;
    for (int kt = 0; kt < nkt; kt++) {
        int k0 = kt << 4;
        #pragma unroll
        for (int t = 0; t < 8; t++) {
            int idx = tid + t * 256;
            int r = idx >> 4, c = idx & 15;
            int gr = rb + r, gk = k0 + c;
            float vv = 0.f;
            if (gr < M && gk < K) vv = A[(size_t)gr * lda + gk];
            As[c][r] = vv;
        }
        #pragma unroll
        for (int t = 0; t < 8; t++) {
            int idx = tid + t * 256;
            float vv = 0.f;
            if (TRANS_B) {
                int n = idx >> 4, c = idx & 15;
                int gn = cb + n, gk = k0 + c;
                if (gn < N && gk < K) vv = Bm[(size_t)gn * ldb + gk];
                Bs[c][n] = vv;
            } else {
                int c = idx >> 7, n = idx & 127;
                int gk = k0 + c, gn = cb + n;
                if (gk < K && gn < N) vv = Bm[(size_t)gk * ldb + gn];
                Bs[c][n] = vv;
            }
        }
        __syncthreads();
        #pragma unroll
        for (int k = 0; k < 16; k++) {
            float4 a0 = *(const float4*)&As[k][ty * 8];
            float4 a1 = *(const float4*)&As[k][ty * 8 + 4];
            float4 b0 = *(const float4*)&Bs[k][tx * 8];
            float4 b1 = *(const float4*)&Bs[k][tx * 8 + 4];
            float a[8] = {a0.x, a0.y, a0.z, a0.w, a1.x, a1.y, a1.z, a1.w};
            float b[8] = {b0.x, b0.y, b0.z, b0.w, b1.x, b1.y, b1.z, b1.w};
            #pragma unroll
            for (int i = 0; i < 8; i++)
                #pragma unroll
                for (int j = 0; j < 8; j++)
                    acc[i][j] = fmaf(a[i], b[j], acc[i][j]);
        }
        __syncthreads();
    }
    #pragma unroll
    for (int i = 0; i < 8; i++) {
        int gr = rb + ty * 8 + i;
        if (gr >= M) continue;
        #pragma unroll
        for (int j = 0; j < 8; j++) {
            int gn = cb + tx * 8 + j;
            if (gn >= N) continue;
            float bv = bias ? bias[gn] : 0.f;
            C[(size_t)gr * ldc + gn] = alpha * acc[i][j] + beta0 + bv;
        }
    }
}

// -------------------- reshape to heads + lift (one warp per (b,h,n)) --------------------
__global__ void headify_k(const float* __restrict__ t, float* __restrict__ dst, float tsgn) {
    int gw = (blockIdx.x * blockDim.x + threadIdx.x) >> 5;
    int lane = threadIdx.x & 31;
    if (gw >= BH * SEQ) return;
    int n = gw & (SEQ - 1);
    int bh = gw >> 10;
    int h = bh & (NH - 1), b = bh >> 4;
    const float* src = t + ((size_t)(b * SEQ + n)) * DM + h * HDIM;
    float v0 = src[lane], v1 = src[32 + lane];
    float s = v0 * v0 + v1 * v1;
    #pragma unroll
    for (int o = 16; o; o >>= 1) s += __shfl_xor_sync(0xffffffffu, s, o);
    float tv = sqrtf(s + 1.0f);
    float* d = dst + (size_t)gw * 65;
    if (lane == 0) d[0] = tsgn * tv;
    d[1 + lane] = v0;
    d[33 + lane] = v1;
}

// -------------------- softmax over last dim (rows of 1024), in place --------------------
__global__ void softmax_k(float* __restrict__ sc) {
    size_t row = blockIdx.x;
    float* r = sc + row * SEQ;
    float v[4];
    float m = -1e30f;
    #pragma unroll
    for (int t = 0; t < 4; t++) { v[t] = r[threadIdx.x + t * 256]; m = fmaxf(m, v[t]); }
    m = blockReduceMax(m);
    float s = 0.f;
    #pragma unroll
    for (int t = 0; t < 4; t++) { v[t] = expf(v[t] - m); s += v[t]; }
    s = blockReduceSum(s);
    float inv = 1.0f / s;
    #pragma unroll
    for (int t = 0; t < 4; t++) r[threadIdx.x + t * 256] = v[t] * inv;
}

// -------------------- mid normalize + transpose into cat (warp per (b,h,n)) --------------------
__global__ void catnorm_k(const float* __restrict__ mid, float* __restrict__ cat) {
    int gw = (blockIdx.x * blockDim.x + threadIdx.x) >> 5;
    int lane = threadIdx.x & 31;
    if (gw >= BH * SEQ) return;
    int n = gw & (SEQ - 1);
    int bh = gw >> 10;
    int h = bh & (NH - 1), b = bh >> 4;
    const float* src = mid + (size_t)gw * 65;
    float t0 = src[0];
    float v0 = src[1 + lane], v1 = src[33 + lane];
    float s = v0 * v0 + v1 * v1;
    #pragma unroll
    for (int o = 16; o; o >>= 1) s += __shfl_xor_sync(0xffffffffu, s, o);
    float nl = t0 * t0 - s;                      // -linner
    float inv = rsqrtf(fmaxf(nl, 1e-8f));
    float* d = cat + ((size_t)(b * SEQ + n)) * CATW + h * 65;
    if (lane == 0) d[0] = t0 * inv;
    d[1 + lane] = v0 * inv;
    d[33 + lane] = v1 * inv;
}

// -------------------- fill time component (col 0) of each row --------------------
__global__ void lift_row_k(float* __restrict__ m, int C) {
    int row = blockIdx.x;
    float* r = m + (size_t)row * C;
    float s = 0.f;
    for (int i = 1 + threadIdx.x; i < C; i += blockDim.x) { float v = r[i]; s += v * v; }
    s = blockReduceSum(s);
    if (threadIdx.x == 0) r[0] = sqrtf(s + 1.0f);
}

// -------------------- Lorentz residual: out = (x + w*y)/sqrt(max(-<z,z>,eps)) --------------------
__global__ void lresnet_k(const float* __restrict__ x, const float* __restrict__ y,
                          const float* __restrict__ wp, float* __restrict__ out) {
    int row = blockIdx.x;
    const float* xr = x + (size_t)row * DM;
    const float* yr = y + (size_t)row * DM;
    float w = *wp;
    float z[4];
    float s = 0.f;
    #pragma unroll
    for (int t = 0; t < 4; t++) {
        int i = threadIdx.x + t * 256;
        float zz = xr[i] + w * yr[i];
        z[t] = zz;
        s += (i == 0) ? zz * zz : -(zz * zz);    // z_t^2 - sum(z_s^2)
    }
    s = blockReduceSum(s);
    float inv = rsqrtf(fmaxf(s, 1e-8f));
    float* o = out + (size_t)row * DM;
    #pragma unroll
    for (int t = 0; t < 4; t++) o[threadIdx.x + t * 256] = z[t] * inv;
}

// -------------------- exact gelu on FF cols + lift into FFL-wide rows --------------------
__global__ void gelu_lift_k(const float* __restrict__ in, float* __restrict__ out) {
    int row = blockIdx.x;
    const float* ir = in + (size_t)row * FF;
    float* orow = out + (size_t)row * FFL;
    float s = 0.f;
    for (int i = threadIdx.x; i < FF; i += blockDim.x) {
        float v = ir[i];
        float g = 0.5f * v * (1.0f + erff(v * 0.70710678118654752f));
        orow[1 + i] = g;
        s += g * g;
    }
    s = blockReduceSum(s);
    if (threadIdx.x == 0) orow[0] = sqrtf(s + 1.0f);
}

// -------------------- host --------------------
static inline int cdiv(int a, int b) { return (a + b - 1) / b; }

extern "C" void kernel_launch(void* const* d_in, const int* in_sizes, int n_in,
                              void* d_out, int out_size) {
    const float* x   = (const float*)d_in[0];
    const float* g1  = (const float*)d_in[1];
    const float* b1  = (const float*)d_in[2];
    const float* Wq  = (const float*)d_in[3];
    const float* bq  = (const float*)d_in[4];
    const float* Wk  = (const float*)d_in[5];
    const float* bk  = (const float*)d_in[6];
    const float* Wv  = (const float*)d_in[7];
    const float* bv  = (const float*)d_in[8];
    const float* Wo  = (const float*)d_in[9];
    const float* bo  = (const float*)d_in[10];
    const float* g2  = (const float*)d_in[11];
    const float* b2  = (const float*)d_in[12];
    const float* Wfc = (const float*)d_in[13];
    const float* bfc = (const float*)d_in[14];
    const float* Wpj = (const float*)d_in[15];
    const float* bpj = (const float*)d_in[16];
    const float* w1  = (const float*)d_in[17];
    const float* w2  = (const float*)d_in[18];
    float* out = (float*)d_out;

    float *lx, *tmp, *q, *k, *v, *sc, *mid, *cat, *ax, *x1, *h, *hfc, *hg, *hpj;
    cudaGetSymbolAddress((void**)&lx,  g_lx);
    cudaGetSymbolAddress((void**)&tmp, g_tmp);
    cudaGetSymbolAddress((void**)&q,   g_q);
    cudaGetSymbolAddress((void**)&k,   g_k);
    cudaGetSymbolAddress((void**)&v,   g_v);
    cudaGetSymbolAddress((void**)&sc,  g_sc);
    cudaGetSymbolAddress((void**)&mid, g_mid);
    cudaGetSymbolAddress((void**)&cat, g_cat);
    cudaGetSymbolAddress((void**)&ax,  g_ax);
    cudaGetSymbolAddress((void**)&x1,  g_x1);
    cudaGetSymbolAddress((void**)&h,   g_h);
    cudaGetSymbolAddress((void**)&hfc, g_hfc);
    cudaGetSymbolAddress((void**)&hg,  g_hg);
    cudaGetSymbolAddress((void**)&hpj, g_hpj);

    // 1. Lorentz layernorm of x -> lx
    ln_lift_k<<<ROWS, 256>>>(x, g1, b1, lx);

    // 2. Q/K/V projections + head split + lift (q stores negated time)
    dim3 gqkv(ROWS / 128, cdiv(DM, 128), 1);
    sgemm_k<false><<<gqkv, 256>>>(lx, Wq, bq, tmp, ROWS, DM, DM, DM, DM, DM, 0, 0, 0, 1.f, 0.f);
    headify_k<<<BH * SEQ / 8, 256>>>(tmp, q, -1.f);
    sgemm_k<false><<<gqkv, 256>>>(lx, Wk, bk, tmp, ROWS, DM, DM, DM, DM, DM, 0, 0, 0, 1.f, 0.f);
    headify_k<<<BH * SEQ / 8, 256>>>(tmp, k, 1.f);
    sgemm_k<false><<<gqkv, 256>>>(lx, Wv, bv, tmp, ROWS, DM, DM, DM, DM, DM, 0, 0, 0, 1.f, 0.f);
    headify_k<<<BH * SEQ / 8, 256>>>(tmp, v, 1.f);

    // 3. scores = (2 + 2 * <q',k>)/sqrt(HD)  => alpha=0.25, beta0=0.25  (batched NT)
    dim3 gsc(SEQ / 128, SEQ / 128, BH);
    sgemm_k<true><<<gsc, 256>>>(q, k, nullptr, sc, SEQ, SEQ, 65, 65, 65, SEQ,
                                (size_t)SEQ * 65, (size_t)SEQ * 65, (size_t)SEQ * SEQ,
                                0.25f, 0.25f);

    // 4. row softmax (in place)
    softmax_k<<<BH * SEQ, 256>>>(sc);

    // 5. mid = attn @ v (batched NN, K=1024, N=65)
    dim3 gmid(SEQ / 128, 1, BH);
    sgemm_k<false><<<gmid, 256>>>(sc, v, nullptr, mid, SEQ, 65, SEQ, SEQ, 65, 65,
                                  (size_t)SEQ * SEQ, (size_t)SEQ * 65, (size_t)SEQ * 65,
                                  1.f, 0.f);

    // 6. Lorentz-normalize mid, transpose heads into cat (B,N,1040)
    catnorm_k<<<BH * SEQ / 8, 256>>>(mid, cat);

    // 7. ax = lift(cat @ Wo + bo): GEMM into cols 1..1023, then time
    dim3 go(ROWS / 128, cdiv(DM - 1, 128), 1);
    sgemm_k<false><<<go, 256>>>(cat, Wo, bo, ax + 1, ROWS, DM - 1, CATW, CATW, DM - 1, DM,
                                0, 0, 0, 1.f, 0.f);
    lift_row_k<<<ROWS, 256>>>(ax, DM);

    // 8. x1 = lresnet(x, ax, w1)
    lresnet_k<<<ROWS, 256>>>(x, ax, w1, x1);

    // 9. h = Lorentz layernorm(x1)
    ln_lift_k<<<ROWS, 256>>>(x1, g2, b2, h);

    // 10. hfc = h @ Wfc + bfc (space part only; first lift's time is discarded by gelu+relift)
    dim3 gfc(ROWS / 128, cdiv(FF, 128), 1);
    sgemm_k<false><<<gfc, 256>>>(h, Wfc, bfc, hfc, ROWS, FF, DM, DM, FF, FF, 0, 0, 0, 1.f, 0.f);

    // 11. hg = lift(gelu(hfc))
    gelu_lift_k<<<ROWS, 256>>>(hfc, hg);

    // 12. hpj = lift(hg @ Wpj + bpj)
    dim3 gpj(ROWS / 128, cdiv(DM - 1, 128), 1);
    sgemm_k<false><<<gpj, 256>>>(hg, Wpj, bpj, hpj + 1, ROWS, DM - 1, FFL, FFL, DM - 1, DM,
                                 0, 0, 0, 1.f, 0.f);
    lift_row_k<<<ROWS, 256>>>(hpj, DM);

    // 13. out = lresnet(x1, hpj, w2)
    lresnet_k<<<ROWS, 256>>>(x1, hpj, w2, out);
}

// round 6
// speedup vs baseline: 1.4953x; 1.4953x over previous
#include <cuda_runtime.h>
#include <cuda_bf16.h>
#include <math.h>

#define BSZ 4
#define SEQ 1024
#define DM 1024
#define NH 16
#define HDIM 64
#define BH (BSZ*NH)            // 64
#define ROWS (BSZ*SEQ)         // 4096
#define CATW (NH*(HDIM+1))     // 1040
#define FF 4095
#define FFL 4096

// -------------------- scratch (static device allocations) --------------------
__device__ float g_lx [ROWS*DM];
__device__ float g_tmp[ROWS*DM];
__device__ float g_q  [BH*SEQ*65];
__device__ float g_k  [BH*SEQ*65];
__device__ float g_v  [BH*SEQ*65];
__device__ float g_sc [(size_t)BH*SEQ*SEQ];       // 256 MB
__device__ float g_mid[BH*SEQ*65];
__device__ float g_cat[ROWS*CATW];
__device__ float g_ax [ROWS*DM];
__device__ float g_x1 [ROWS*DM];
__device__ float g_h  [ROWS*DM];
__device__ float g_hfc[(size_t)ROWS*FF];
__device__ float g_hg [(size_t)ROWS*FFL];
__device__ float g_hpj[ROWS*DM];

// -------------------- reductions --------------------
__device__ __forceinline__ float warpReduceSum(float v) {
    #pragma unroll
    for (int o = 16; o; o >>= 1) v += __shfl_xor_sync(0xffffffffu, v, o);
    return v;
}
__device__ __forceinline__ float warpReduceMax(float v) {
    #pragma unroll
    for (int o = 16; o; o >>= 1) v = fmaxf(v, __shfl_xor_sync(0xffffffffu, v, o));
    return v;
}
__device__ float blockReduceSum(float v) {
    __shared__ float sbuf[32];
    __shared__ float res;
    int lane = threadIdx.x & 31, wid = threadIdx.x >> 5;
    v = warpReduceSum(v);
    if (lane == 0) sbuf[wid] = v;
    __syncthreads();
    if (wid == 0) {
        float t = (lane < ((int)blockDim.x >> 5)) ? sbuf[lane] : 0.f;
        t = warpReduceSum(t);
        if (lane == 0) res = t;
    }
    __syncthreads();
    float r = res;
    __syncthreads();
    return r;
}
__device__ float blockReduceMax(float v) {
    __shared__ float sbuf[32];
    __shared__ float res;
    int lane = threadIdx.x & 31, wid = threadIdx.x >> 5;
    v = warpReduceMax(v);
    if (lane == 0) sbuf[wid] = v;
    __syncthreads();
    if (wid == 0) {
        float t = (lane < ((int)blockDim.x >> 5)) ? sbuf[lane] : -1e30f;
        t = warpReduceMax(t);
        if (lane == 0) res = t;
    }
    __syncthreads();
    float r = res;
    __syncthreads();
    return r;
}

// -------------------- Lorentz layernorm + lift --------------------
__global__ void ln_lift_k(const float* __restrict__ x, const float* __restrict__ gamma,
                          const float* __restrict__ beta, float* __restrict__ out) {
    int row = blockIdx.x;
    const float* xs = x + (size_t)row * DM + 1;
    float* os = out + (size_t)row * DM;
    float s = 0.f;
    for (int i = threadIdx.x; i < DM - 1; i += blockDim.x) s += xs[i];
    s = blockReduceSum(s);
    float mu = s * (1.0f / (DM - 1));
    float v = 0.f;
    for (int i = threadIdx.x; i < DM - 1; i += blockDim.x) {
        float d = xs[i] - mu; v += d * d;
    }
    v = blockReduceSum(v);
    float rstd = rsqrtf(v * (1.0f / (DM - 1)) + 1e-5f);
    float sq = 0.f;
    for (int i = threadIdx.x; i < DM - 1; i += blockDim.x) {
        float y = (xs[i] - mu) * rstd * gamma[i] + beta[i];
        os[i + 1] = y;
        sq += y * y;
    }
    sq = blockReduceSum(sq);
    if (threadIdx.x == 0) os[0] = sqrtf(sq + 1.0f);
}

// -------------------- double-buffered SGEMM 128x128x16, 8x8/thread --------------------
// C[m][n] = alpha * sum_k A[m][k]*B(k,n) + beta0 + bias[n]
// TRANS_B=false: B is K x N.  TRANS_B=true: B is N x K.
template <bool TRANS_B>
__global__ void sgemm_k(const float* __restrict__ A, const float* __restrict__ Bm,
                        const float* __restrict__ bias, float* __restrict__ C,
                        int M, int N, int K, int lda, int ldb, int ldc,
                        size_t sA, size_t sB, size_t sC, float alpha, float beta0) {
    __shared__ float As[2][16][132];
    __shared__ float Bs[2][16][132];
    A  += blockIdx.z * sA;
    Bm += blockIdx.z * sB;
    C  += blockIdx.z * sC;
    int rb = blockIdx.x * 128, cb = blockIdx.y * 128;
    int tid = threadIdx.x;
    int tx = tid & 15, ty = tid >> 4;
    float acc[8][8] = {};
    int nkt = (K + 15) >> 4;

    float ra[8], rbv[8];

    // ---- prefetch tile 0 into regs ----
    {
        int k0 = 0;
        #pragma unroll
        for (int t = 0; t < 8; t++) {
            int idx = tid + t * 256;
            int r = idx >> 4, c = idx & 15;
            int gr = rb + r, gk = k0 + c;
            ra[t] = (gr < M && gk < K) ? A[(size_t)gr * lda + gk] : 0.f;
        }
        #pragma unroll
        for (int t = 0; t < 8; t++) {
            int idx = tid + t * 256;
            if (TRANS_B) {
                int n = idx >> 4, c = idx & 15;
                int gn = cb + n, gk = k0 + c;
                rbv[t] = (gn < N && gk < K) ? Bm[(size_t)gn * ldb + gk] : 0.f;
            } else {
                int c = idx >> 7, n = idx & 127;
                int gk = k0 + c, gn = cb + n;
                rbv[t] = (gk < K && gn < N) ? Bm[(size_t)gk * ldb + gn] : 0.f;
            }
        }
    }
    // ---- store tile 0 ----
    #pragma unroll
    for (int t = 0; t < 8; t++) {
        int idx = tid + t * 256;
        As[0][idx & 15][idx >> 4] = ra[t];
    }
    #pragma unroll
    for (int t = 0; t < 8; t++) {
        int idx = tid + t * 256;
        if (TRANS_B) Bs[0][idx & 15][idx >> 4] = rbv[t];
        else         Bs[0][idx >> 7][idx & 127] = rbv[t];
    }
    __syncthreads();

    #pragma unroll 1
    for (int kt = 0; kt < nkt; kt++) {
        int cur = kt & 1, nxt = cur ^ 1;
        bool more = (kt + 1 < nkt);
        // ---- prefetch next tile into regs (overlaps compute) ----
        if (more) {
            int k0 = (kt + 1) << 4;
            #pragma unroll
            for (int t = 0; t < 8; t++) {
                int idx = tid + t * 256;
                int r = idx >> 4, c = idx & 15;
                int gr = rb + r, gk = k0 + c;
                ra[t] = (gr < M && gk < K) ? A[(size_t)gr * lda + gk] : 0.f;
            }
            #pragma unroll
            for (int t = 0; t < 8; t++) {
                int idx = tid + t * 256;
                if (TRANS_B) {
                    int n = idx >> 4, c = idx & 15;
                    int gn = cb + n, gk = k0 + c;
                    rbv[t] = (gn < N && gk < K) ? Bm[(size_t)gn * ldb + gk] : 0.f;
                } else {
                    int c = idx >> 7, n = idx & 127;
                    int gk = k0 + c, gn = cb + n;
                    rbv[t] = (gk < K && gn < N) ? Bm[(size_t)gk * ldb + gn] : 0.f;
                }
            }
        }
        // ---- compute current tile ----
        #pragma unroll
        for (int k = 0; k < 16; k++) {
            float4 a0 = *(const float4*)&As[cur][k][ty * 8];
            float4 a1 = *(const float4*)&As[cur][k][ty * 8 + 4];
            float4 b0 = *(const float4*)&Bs[cur][k][tx * 8];
            float4 b1 = *(const float4*)&Bs[cur][k][tx * 8 + 4];
            float a[8] = {a0.x, a0.y, a0.z, a0.w, a1.x, a1.y, a1.z, a1.w};
            float b[8] = {b0.x, b0.y, b0.z, b0.w, b1.x, b1.y, b1.z, b1.w};
            #pragma unroll
            for (int i = 0; i < 8; i++)
                #pragma unroll
                for (int j = 0; j < 8; j++)
                    acc[i][j] = fmaf(a[i], b[j], acc[i][j]);
        }
        // ---- store next tile into the other buffer ----
        if (more) {
            #pragma unroll
            for (int t = 0; t < 8; t++) {
                int idx = tid + t * 256;
                As[nxt][idx & 15][idx >> 4] = ra[t];
            }
            #pragma unroll
            for (int t = 0; t < 8; t++) {
                int idx = tid + t * 256;
                if (TRANS_B) Bs[nxt][idx & 15][idx >> 4] = rbv[t];
                else         Bs[nxt][idx >> 7][idx & 127] = rbv[t];
            }
        }
        __syncthreads();
    }

    #pragma unroll
    for (int i = 0; i < 8; i++) {
        int gr = rb + ty * 8 + i;
        if (gr >= M) continue;
        #pragma unroll
        for (int j = 0; j < 8; j++) {
            int gn = cb + tx * 8 + j;
            if (gn >= N) continue;
            float bv = bias ? bias[gn] : 0.f;
            C[(size_t)gr * ldc + gn] = alpha * acc[i][j] + beta0 + bv;
        }
    }
}

// -------------------- reshape to heads + lift (one warp per (b,h,n)) --------------------
__global__ void headify_k(const float* __restrict__ t, float* __restrict__ dst, float tsgn) {
    int gw = (blockIdx.x * blockDim.x + threadIdx.x) >> 5;
    int lane = threadIdx.x & 31;
    if (gw >= BH * SEQ) return;
    int n = gw & (SEQ - 1);
    int bh = gw >> 10;
    int h = bh & (NH - 1), b = bh >> 4;
    const float* src = t + ((size_t)(b * SEQ + n)) * DM + h * HDIM;
    float v0 = src[lane], v1 = src[32 + lane];
    float s = v0 * v0 + v1 * v1;
    #pragma unroll
    for (int o = 16; o; o >>= 1) s += __shfl_xor_sync(0xffffffffu, s, o);
    float tv = sqrtf(s + 1.0f);
    float* d = dst + (size_t)gw * 65;
    if (lane == 0) d[0] = tsgn * tv;
    d[1 + lane] = v0;
    d[33 + lane] = v1;
}

// -------------------- softmax over last dim (rows of 1024), in place --------------------
__global__ void softmax_k(float* __restrict__ sc) {
    size_t row = blockIdx.x;
    float* r = sc + row * SEQ;
    float v[4];
    float m = -1e30f;
    #pragma unroll
    for (int t = 0; t < 4; t++) { v[t] = r[threadIdx.x + t * 256]; m = fmaxf(m, v[t]); }
    m = blockReduceMax(m);
    float s = 0.f;
    #pragma unroll
    for (int t = 0; t < 4; t++) { v[t] = expf(v[t] - m); s += v[t]; }
    s = blockReduceSum(s);
    float inv = 1.0f / s;
    #pragma unroll
    for (int t = 0; t < 4; t++) r[threadIdx.x + t * 256] = v[t] * inv;
}

// -------------------- mid normalize + transpose into cat (warp per (b,h,n)) --------------------
__global__ void catnorm_k(const float* __restrict__ mid, float* __restrict__ cat) {
    int gw = (blockIdx.x * blockDim.x + threadIdx.x) >> 5;
    int lane = threadIdx.x & 31;
    if (gw >= BH * SEQ) return;
    int n = gw & (SEQ - 1);
    int bh = gw >> 10;
    int h = bh & (NH - 1), b = bh >> 4;
    const float* src = mid + (size_t)gw * 65;
    float t0 = src[0];
    float v0 = src[1 + lane], v1 = src[33 + lane];
    float s = v0 * v0 + v1 * v1;
    #pragma unroll
    for (int o = 16; o; o >>= 1) s += __shfl_xor_sync(0xffffffffu, s, o);
    float nl = t0 * t0 - s;                      // -linner
    float inv = rsqrtf(fmaxf(nl, 1e-8f));
    float* d = cat + ((size_t)(b * SEQ + n)) * CATW + h * 65;
    if (lane == 0) d[0] = t0 * inv;
    d[1 + lane] = v0 * inv;
    d[33 + lane] = v1 * inv;
}

// -------------------- fill time component (col 0) of each row --------------------
__global__ void lift_row_k(float* __restrict__ m, int C) {
    int row = blockIdx.x;
    float* r = m + (size_t)row * C;
    float s = 0.f;
    for (int i = 1 + threadIdx.x; i < C; i += blockDim.x) { float v = r[i]; s += v * v; }
    s = blockReduceSum(s);
    if (threadIdx.x == 0) r[0] = sqrtf(s + 1.0f);
}

// -------------------- Lorentz residual: out = (x + w*y)/sqrt(max(-<z,z>,eps)) --------------------
__global__ void lresnet_k(const float* __restrict__ x, const float* __restrict__ y,
                          const float* __restrict__ wp, float* __restrict__ out) {
    int row = blockIdx.x;
    const float* xr = x + (size_t)row * DM;
    const float* yr = y + (size_t)row * DM;
    float w = *wp;
    float z[4];
    float s = 0.f;
    #pragma unroll
    for (int t = 0; t < 4; t++) {
        int i = threadIdx.x + t * 256;
        float zz = xr[i] + w * yr[i];
        z[t] = zz;
        s += (i == 0) ? zz * zz : -(zz * zz);    // z_t^2 - sum(z_s^2)
    }
    s = blockReduceSum(s);
    float inv = rsqrtf(fmaxf(s, 1e-8f));
    float* o = out + (size_t)row * DM;
    #pragma unroll
    for (int t = 0; t < 4; t++) o[threadIdx.x + t * 256] = z[t] * inv;
}

// -------------------- exact gelu on FF cols + lift into FFL-wide rows --------------------
__global__ void gelu_lift_k(const float* __restrict__ in, float* __restrict__ out) {
    int row = blockIdx.x;
    const float* ir = in + (size_t)row * FF;
    float* orow = out + (size_t)row * FFL;
    float s = 0.f;
    for (int i = threadIdx.x; i < FF; i += blockDim.x) {
        float v = ir[i];
        float g = 0.5f * v * (1.0f + erff(v * 0.70710678118654752f));
        orow[1 + i] = g;
        s += g * g;
    }
    s = blockReduceSum(s);
    if (threadIdx.x == 0) orow[0] = sqrtf(s + 1.0f);
}

// -------------------- host --------------------
static inline int cdiv(int a, int b) { return (a + b - 1) / b; }

extern "C" void kernel_launch(void* const* d_in, const int* in_sizes, int n_in,
                              void* d_out, int out_size) {
    const float* x   = (const float*)d_in[0];
    const float* g1  = (const float*)d_in[1];
    const float* b1  = (const float*)d_in[2];
    const float* Wq  = (const float*)d_in[3];
    const float* bq  = (const float*)d_in[4];
    const float* Wk  = (const float*)d_in[5];
    const float* bk  = (const float*)d_in[6];
    const float* Wv  = (const float*)d_in[7];
    const float* bv  = (const float*)d_in[8];
    const float* Wo  = (const float*)d_in[9];
    const float* bo  = (const float*)d_in[10];
    const float* g2  = (const float*)d_in[11];
    const float* b2  = (const float*)d_in[12];
    const float* Wfc = (const float*)d_in[13];
    const float* bfc = (const float*)d_in[14];
    const float* Wpj = (const float*)d_in[15];
    const float* bpj = (const float*)d_in[16];
    const float* w1  = (const float*)d_in[17];
    const float* w2  = (const float*)d_in[18];
    float* out = (float*)d_out;

    float *lx, *tmp, *q, *k, *v, *sc, *mid, *cat, *ax, *x1, *h, *hfc, *hg, *hpj;
    cudaGetSymbolAddress((void**)&lx,  g_lx);
    cudaGetSymbolAddress((void**)&tmp, g_tmp);
    cudaGetSymbolAddress((void**)&q,   g_q);
    cudaGetSymbolAddress((void**)&k,   g_k);
    cudaGetSymbolAddress((void**)&v,   g_v);
    cudaGetSymbolAddress((void**)&sc,  g_sc);
    cudaGetSymbolAddress((void**)&mid, g_mid);
    cudaGetSymbolAddress((void**)&cat, g_cat);
    cudaGetSymbolAddress((void**)&ax,  g_ax);
    cudaGetSymbolAddress((void**)&x1,  g_x1);
    cudaGetSymbolAddress((void**)&h,   g_h);
    cudaGetSymbolAddress((void**)&hfc, g_hfc);
    cudaGetSymbolAddress((void**)&hg,  g_hg);
    cudaGetSymbolAddress((void**)&hpj, g_hpj);

    // 1. Lorentz layernorm of x -> lx
    ln_lift_k<<<ROWS, 256>>>(x, g1, b1, lx);

    // 2. Q/K/V projections + head split + lift (q stores negated time)
    dim3 gqkv(ROWS / 128, cdiv(DM, 128), 1);
    sgemm_k<false><<<gqkv, 256>>>(lx, Wq, bq, tmp, ROWS, DM, DM, DM, DM, DM, 0, 0, 0, 1.f, 0.f);
    headify_k<<<BH * SEQ / 8, 256>>>(tmp, q, -1.f);
    sgemm_k<false><<<gqkv, 256>>>(lx, Wk, bk, tmp, ROWS, DM, DM, DM, DM, DM, 0, 0, 0, 1.f, 0.f);
    headify_k<<<BH * SEQ / 8, 256>>>(tmp, k, 1.f);
    sgemm_k<false><<<gqkv, 256>>>(lx, Wv, bv, tmp, ROWS, DM, DM, DM, DM, DM, 0, 0, 0, 1.f, 0.f);
    headify_k<<<BH * SEQ / 8, 256>>>(tmp, v, 1.f);

    // 3. scores = (2 + 2 * <q',k>)/sqrt(HD)  => alpha=0.25, beta0=0.25  (batched NT)
    dim3 gsc(SEQ / 128, SEQ / 128, BH);
    sgemm_k<true><<<gsc, 256>>>(q, k, nullptr, sc, SEQ, SEQ, 65, 65, 65, SEQ,
                                (size_t)SEQ * 65, (size_t)SEQ * 65, (size_t)SEQ * SEQ,
                                0.25f, 0.25f);

    // 4. row softmax (in place)
    softmax_k<<<BH * SEQ, 256>>>(sc);

    // 5. mid = attn @ v (batched NN, K=1024, N=65)
    dim3 gmid(SEQ / 128, 1, BH);
    sgemm_k<false><<<gmid, 256>>>(sc, v, nullptr, mid, SEQ, 65, SEQ, SEQ, 65, 65,
                                  (size_t)SEQ * SEQ, (size_t)SEQ * 65, (size_t)SEQ * 65,
                                  1.f, 0.f);

    // 6. Lorentz-normalize mid, transpose heads into cat (B,N,1040)
    catnorm_k<<<BH * SEQ / 8, 256>>>(mid, cat);

    // 7. ax = lift(cat @ Wo + bo): GEMM into cols 1..1023, then time
    dim3 go(ROWS / 128, cdiv(DM - 1, 128), 1);
    sgemm_k<false><<<go, 256>>>(cat, Wo, bo, ax + 1, ROWS, DM - 1, CATW, CATW, DM - 1, DM,
                                0, 0, 0, 1.f, 0.f);
    lift_row_k<<<ROWS, 256>>>(ax, DM);

    // 8. x1 = lresnet(x, ax, w1)
    lresnet_k<<<ROWS, 256>>>(x, ax, w1, x1);

    // 9. h = Lorentz layernorm(x1)
    ln_lift_k<<<ROWS, 256>>>(x1, g2, b2, h);

    // 10. hfc = h @ Wfc + bfc
    dim3 gfc(ROWS / 128, cdiv(FF, 128), 1);
    sgemm_k<false><<<gfc, 256>>>(h, Wfc, bfc, hfc, ROWS, FF, DM, DM, FF, FF, 0, 0, 0, 1.f, 0.f);

    // 11. hg = lift(gelu(hfc))
    gelu_lift_k<<<ROWS, 256>>>(hfc, hg);

    // 12. hpj = lift(hg @ Wpj + bpj)
    dim3 gpj(ROWS / 128, cdiv(DM - 1, 128), 1);
    sgemm_k<false><<<gpj, 256>>>(hg, Wpj, bpj, hpj + 1, ROWS, DM - 1, FFL, FFL, DM - 1, DM,
                                 0, 0, 0, 1.f, 0.f);
    lift_row_k<<<ROWS, 256>>>(hpj, DM);

    // 13. out = lresnet(x1, hpj, w2)
    lresnet_k<<<ROWS, 256>>>(x1, hpj, w2, out);
}

// round 9
// speedup vs baseline: 1.8162x; 1.2146x over previous
#include <cuda_runtime.h>
#include <cuda_bf16.h>
#include <math.h>

#define BSZ 4
#define SEQ 1024
#define DM 1024
#define NH 16
#define HDIM 64
#define BH (BSZ*NH)            // 64
#define ROWS (BSZ*SEQ)         // 4096
#define CATW (NH*(HDIM+1))     // 1040
#define FF 4095
#define FFL 4096

// -------------------- scratch (static device allocations) --------------------
__device__ float g_lx [ROWS*DM];
__device__ float g_tmp[ROWS*DM];
__device__ float g_q  [BH*SEQ*65];
__device__ float g_k  [BH*SEQ*65];
__device__ float g_v  [BH*SEQ*65];
__device__ float g_sc [(size_t)BH*SEQ*SEQ];       // 256 MB
__device__ float g_mid[BH*SEQ*65];
__device__ float g_cat[ROWS*CATW];
__device__ float g_ax [ROWS*DM];
__device__ float g_x1 [ROWS*DM];
__device__ float g_h  [ROWS*DM];
__device__ float g_hfc[(size_t)ROWS*FF];
__device__ float g_hg [(size_t)ROWS*FFL];
__device__ float g_hpj[ROWS*DM];

// -------------------- reductions --------------------
__device__ __forceinline__ float warpReduceSum(float v) {
    #pragma unroll
    for (int o = 16; o; o >>= 1) v += __shfl_xor_sync(0xffffffffu, v, o);
    return v;
}
__device__ __forceinline__ float warpReduceMax(float v) {
    #pragma unroll
    for (int o = 16; o; o >>= 1) v = fmaxf(v, __shfl_xor_sync(0xffffffffu, v, o));
    return v;
}
__device__ float blockReduceSum(float v) {
    __shared__ float sbuf[32];
    __shared__ float res;
    int lane = threadIdx.x & 31, wid = threadIdx.x >> 5;
    v = warpReduceSum(v);
    if (lane == 0) sbuf[wid] = v;
    __syncthreads();
    if (wid == 0) {
        float t = (lane < ((int)blockDim.x >> 5)) ? sbuf[lane] : 0.f;
        t = warpReduceSum(t);
        if (lane == 0) res = t;
    }
    __syncthreads();
    float r = res;
    __syncthreads();
    return r;
}
__device__ float blockReduceMax(float v) {
    __shared__ float sbuf[32];
    __shared__ float res;
    int lane = threadIdx.x & 31, wid = threadIdx.x >> 5;
    v = warpReduceMax(v);
    if (lane == 0) sbuf[wid] = v;
    __syncthreads();
    if (wid == 0) {
        float t = (lane < ((int)blockDim.x >> 5)) ? sbuf[lane] : -1e30f;
        t = warpReduceMax(t);
        if (lane == 0) res = t;
    }
    __syncthreads();
    float r = res;
    __syncthreads();
    return r;
}

// -------------------- Lorentz layernorm + lift --------------------
__global__ void ln_lift_k(const float* __restrict__ x, const float* __restrict__ gamma,
                          const float* __restrict__ beta, float* __restrict__ out) {
    int row = blockIdx.x;
    const float* xs = x + (size_t)row * DM + 1;
    float* os = out + (size_t)row * DM;
    float s = 0.f;
    for (int i = threadIdx.x; i < DM - 1; i += blockDim.x) s += xs[i];
    s = blockReduceSum(s);
    float mu = s * (1.0f / (DM - 1));
    float v = 0.f;
    for (int i = threadIdx.x; i < DM - 1; i += blockDim.x) {
        float d = xs[i] - mu; v += d * d;
    }
    v = blockReduceSum(v);
    float rstd = rsqrtf(v * (1.0f / (DM - 1)) + 1e-5f);
    float sq = 0.f;
    for (int i = threadIdx.x; i < DM - 1; i += blockDim.x) {
        float y = (xs[i] - mu) * rstd * gamma[i] + beta[i];
        os[i + 1] = y;
        sq += y * y;
    }
    sq = blockReduceSum(sq);
    if (threadIdx.x == 0) os[0] = sqrtf(sq + 1.0f);
}

// -------------------- double-buffered SGEMM 128x128x16, 8x8/thread, 2 CTAs/SM --------------------
// C[m][n] = alpha * sum_k A[m][k]*B(k,n) + beta0 + bias[n]
// TRANS_B=false: B is K x N.  TRANS_B=true: B is N x K.
template <bool TRANS_B>
__global__ void __launch_bounds__(256, 2)
sgemm_k(const float* __restrict__ A, const float* __restrict__ Bm,
        const float* __restrict__ bias, float* __restrict__ C,
        int M, int N, int K, int lda, int ldb, int ldc,
        size_t sA, size_t sB, size_t sC, float alpha, float beta0) {
    __shared__ float As[2][16][132];
    __shared__ float Bs[2][16][132];
    A  += blockIdx.z * sA;
    Bm += blockIdx.z * sB;
    C  += blockIdx.z * sC;
    int rb = blockIdx.x * 128, cb = blockIdx.y * 128;
    int tid = threadIdx.x;
    int tx = tid & 15, ty = tid >> 4;
    float acc[8][8] = {};
    int nkt = (K + 15) >> 4;

    float ra[8], rbv[8];

    // ---- prefetch tile 0 into regs ----
    {
        int k0 = 0;
        #pragma unroll
        for (int t = 0; t < 8; t++) {
            int idx = tid + t * 256;
            int r = idx >> 4, c = idx & 15;
            int gr = rb + r, gk = k0 + c;
            ra[t] = (gr < M && gk < K) ? A[(size_t)gr * lda + gk] : 0.f;
        }
        #pragma unroll
        for (int t = 0; t < 8; t++) {
            int idx = tid + t * 256;
            if (TRANS_B) {
                int n = idx >> 4, c = idx & 15;
                int gn = cb + n, gk = k0 + c;
                rbv[t] = (gn < N && gk < K) ? Bm[(size_t)gn * ldb + gk] : 0.f;
            } else {
                int c = idx >> 7, n = idx & 127;
                int gk = k0 + c, gn = cb + n;
                rbv[t] = (gk < K && gn < N) ? Bm[(size_t)gk * ldb + gn] : 0.f;
            }
        }
    }
    // ---- store tile 0 ----
    #pragma unroll
    for (int t = 0; t < 8; t++) {
        int idx = tid + t * 256;
        As[0][idx & 15][idx >> 4] = ra[t];
    }
    #pragma unroll
    for (int t = 0; t < 8; t++) {
        int idx = tid + t * 256;
        if (TRANS_B) Bs[0][idx & 15][idx >> 4] = rbv[t];
        else         Bs[0][idx >> 7][idx & 127] = rbv[t];
    }
    __syncthreads();

    #pragma unroll 1
    for (int kt = 0; kt < nkt; kt++) {
        int cur = kt & 1, nxt = cur ^ 1;
        bool more = (kt + 1 < nkt);
        // ---- prefetch next tile into regs (overlaps compute) ----
        if (more) {
            int k0 = (kt + 1) << 4;
            #pragma unroll
            for (int t = 0; t < 8; t++) {
                int idx = tid + t * 256;
                int r = idx >> 4, c = idx & 15;
                int gr = rb + r, gk = k0 + c;
                ra[t] = (gr < M && gk < K) ? A[(size_t)gr * lda + gk] : 0.f;
            }
            #pragma unroll
            for (int t = 0; t < 8; t++) {
                int idx = tid + t * 256;
                if (TRANS_B) {
                    int n = idx >> 4, c = idx & 15;
                    int gn = cb + n, gk = k0 + c;
                    rbv[t] = (gn < N && gk < K) ? Bm[(size_t)gn * ldb + gk] : 0.f;
                } else {
                    int c = idx >> 7, n = idx & 127;
                    int gk = k0 + c, gn = cb + n;
                    rbv[t] = (gk < K && gn < N) ? Bm[(size_t)gk * ldb + gn] : 0.f;
                }
            }
        }
        // ---- compute current tile ----
        #pragma unroll
        for (int k = 0; k < 16; k++) {
            float4 a0 = *(const float4*)&As[cur][k][ty * 8];
            float4 a1 = *(const float4*)&As[cur][k][ty * 8 + 4];
            float4 b0 = *(const float4*)&Bs[cur][k][tx * 8];
            float4 b1 = *(const float4*)&Bs[cur][k][tx * 8 + 4];
            float a[8] = {a0.x, a0.y, a0.z, a0.w, a1.x, a1.y, a1.z, a1.w};
            float b[8] = {b0.x, b0.y, b0.z, b0.w, b1.x, b1.y, b1.z, b1.w};
            #pragma unroll
            for (int i = 0; i < 8; i++)
                #pragma unroll
                for (int j = 0; j < 8; j++)
                    acc[i][j] = fmaf(a[i], b[j], acc[i][j]);
        }
        // ---- store next tile into the other buffer ----
        if (more) {
            #pragma unroll
            for (int t = 0; t < 8; t++) {
                int idx = tid + t * 256;
                As[nxt][idx & 15][idx >> 4] = ra[t];
            }
            #pragma unroll
            for (int t = 0; t < 8; t++) {
                int idx = tid + t * 256;
                if (TRANS_B) Bs[nxt][idx & 15][idx >> 4] = rbv[t];
                else         Bs[nxt][idx >> 7][idx & 127] = rbv[t];
            }
        }
        __syncthreads();
    }

    #pragma unroll
    for (int i = 0; i < 8; i++) {
        int gr = rb + ty * 8 + i;
        if (gr >= M) continue;
        #pragma unroll
        for (int j = 0; j < 8; j++) {
            int gn = cb + tx * 8 + j;
            if (gn >= N) continue;
            float bv = bias ? bias[gn] : 0.f;
            C[(size_t)gr * ldc + gn] = alpha * acc[i][j] + beta0 + bv;
        }
    }
}

// -------------------- reshape to heads + lift (one warp per (b,h,n)) --------------------
__global__ void headify_k(const float* __restrict__ t, float* __restrict__ dst, float tsgn) {
    int gw = (blockIdx.x * blockDim.x + threadIdx.x) >> 5;
    int lane = threadIdx.x & 31;
    if (gw >= BH * SEQ) return;
    int n = gw & (SEQ - 1);
    int bh = gw >> 10;
    int h = bh & (NH - 1), b = bh >> 4;
    const float* src = t + ((size_t)(b * SEQ + n)) * DM + h * HDIM;
    float v0 = src[lane], v1 = src[32 + lane];
    float s = v0 * v0 + v1 * v1;
    #pragma unroll
    for (int o = 16; o; o >>= 1) s += __shfl_xor_sync(0xffffffffu, s, o);
    float tv = sqrtf(s + 1.0f);
    float* d = dst + (size_t)gw * 65;
    if (lane == 0) d[0] = tsgn * tv;
    d[1 + lane] = v0;
    d[33 + lane] = v1;
}

// -------------------- softmax over last dim (rows of 1024), in place --------------------
__global__ void softmax_k(float* __restrict__ sc) {
    size_t row = blockIdx.x;
    float* r = sc + row * SEQ;
    float v[4];
    float m = -1e30f;
    #pragma unroll
    for (int t = 0; t < 4; t++) { v[t] = r[threadIdx.x + t * 256]; m = fmaxf(m, v[t]); }
    m = blockReduceMax(m);
    float s = 0.f;
    #pragma unroll
    for (int t = 0; t < 4; t++) { v[t] = expf(v[t] - m); s += v[t]; }
    s = blockReduceSum(s);
    float inv = 1.0f / s;
    #pragma unroll
    for (int t = 0; t < 4; t++) r[threadIdx.x + t * 256] = v[t] * inv;
}

// -------------------- mid normalize + transpose into cat (warp per (b,h,n)) --------------------
__global__ void catnorm_k(const float* __restrict__ mid, float* __restrict__ cat) {
    int gw = (blockIdx.x * blockDim.x + threadIdx.x) >> 5;
    int lane = threadIdx.x & 31;
    if (gw >= BH * SEQ) return;
    int n = gw & (SEQ - 1);
    int bh = gw >> 10;
    int h = bh & (NH - 1), b = bh >> 4;
    const float* src = mid + (size_t)gw * 65;
    float t0 = src[0];
    float v0 = src[1 + lane], v1 = src[33 + lane];
    float s = v0 * v0 + v1 * v1;
    #pragma unroll
    for (int o = 16; o; o >>= 1) s += __shfl_xor_sync(0xffffffffu, s, o);
    float nl = t0 * t0 - s;                      // -linner
    float inv = rsqrtf(fmaxf(nl, 1e-8f));
    float* d = cat + ((size_t)(b * SEQ + n)) * CATW + h * 65;
    if (lane == 0) d[0] = t0 * inv;
    d[1 + lane] = v0 * inv;
    d[33 + lane] = v1 * inv;
}

// -------------------- fill time component (col 0) of each row --------------------
__global__ void lift_row_k(float* __restrict__ m, int C) {
    int row = blockIdx.x;
    float* r = m + (size_t)row * C;
    float s = 0.f;
    for (int i = 1 + threadIdx.x; i < C; i += blockDim.x) { float v = r[i]; s += v * v; }
    s = blockReduceSum(s);
    if (threadIdx.x == 0) r[0] = sqrtf(s + 1.0f);
}

// -------------------- Lorentz residual: out = (x + w*y)/sqrt(max(-<z,z>,eps)) --------------------
__global__ void lresnet_k(const float* __restrict__ x, const float* __restrict__ y,
                          const float* __restrict__ wp, float* __restrict__ out) {
    int row = blockIdx.x;
    const float* xr = x + (size_t)row * DM;
    const float* yr = y + (size_t)row * DM;
    float w = *wp;
    float z[4];
    float s = 0.f;
    #pragma unroll
    for (int t = 0; t < 4; t++) {
        int i = threadIdx.x + t * 256;
        float zz = xr[i] + w * yr[i];
        z[t] = zz;
        s += (i == 0) ? zz * zz : -(zz * zz);    // z_t^2 - sum(z_s^2)
    }
    s = blockReduceSum(s);
    float inv = rsqrtf(fmaxf(s, 1e-8f));
    float* o = out + (size_t)row * DM;
    #pragma unroll
    for (int t = 0; t < 4; t++) o[threadIdx.x + t * 256] = z[t] * inv;
}

// -------------------- exact gelu on FF cols + lift into FFL-wide rows --------------------
__global__ void gelu_lift_k(const float* __restrict__ in, float* __restrict__ out) {
    int row = blockIdx.x;
    const float* ir = in + (size_t)row * FF;
    float* orow = out + (size_t)row * FFL;
    float s = 0.f;
    for (int i = threadIdx.x; i < FF; i += blockDim.x) {
        float v = ir[i];
        float g = 0.5f * v * (1.0f + erff(v * 0.70710678118654752f));
        orow[1 + i] = g;
        s += g * g;
    }
    s = blockReduceSum(s);
    if (threadIdx.x == 0) orow[0] = sqrtf(s + 1.0f);
}

// -------------------- host --------------------
static inline int cdiv(int a, int b) { return (a + b - 1) / b; }

extern "C" void kernel_launch(void* const* d_in, const int* in_sizes, int n_in,
                              void* d_out, int out_size) {
    const float* x   = (const float*)d_in[0];
    const float* g1  = (const float*)d_in[1];
    const float* b1  = (const float*)d_in[2];
    const float* Wq  = (const float*)d_in[3];
    const float* bq  = (const float*)d_in[4];
    const float* Wk  = (const float*)d_in[5];
    const float* bk  = (const float*)d_in[6];
    const float* Wv  = (const float*)d_in[7];
    const float* bv  = (const float*)d_in[8];
    const float* Wo  = (const float*)d_in[9];
    const float* bo  = (const float*)d_in[10];
    const float* g2  = (const float*)d_in[11];
    const float* b2  = (const float*)d_in[12];
    const float* Wfc = (const float*)d_in[13];
    const float* bfc = (const float*)d_in[14];
    const float* Wpj = (const float*)d_in[15];
    const float* bpj = (const float*)d_in[16];
    const float* w1  = (const float*)d_in[17];
    const float* w2  = (const float*)d_in[18];
    float* out = (float*)d_out;

    float *lx, *tmp, *q, *k, *v, *sc, *mid, *cat, *ax, *x1, *h, *hfc, *hg, *hpj;
    cudaGetSymbolAddress((void**)&lx,  g_lx);
    cudaGetSymbolAddress((void**)&tmp, g_tmp);
    cudaGetSymbolAddress((void**)&q,   g_q);
    cudaGetSymbolAddress((void**)&k,   g_k);
    cudaGetSymbolAddress((void**)&v,   g_v);
    cudaGetSymbolAddress((void**)&sc,  g_sc);
    cudaGetSymbolAddress((void**)&mid, g_mid);
    cudaGetSymbolAddress((void**)&cat, g_cat);
    cudaGetSymbolAddress((void**)&ax,  g_ax);
    cudaGetSymbolAddress((void**)&x1,  g_x1);
    cudaGetSymbolAddress((void**)&h,   g_h);
    cudaGetSymbolAddress((void**)&hfc, g_hfc);
    cudaGetSymbolAddress((void**)&hg,  g_hg);
    cudaGetSymbolAddress((void**)&hpj, g_hpj);

    // 1. Lorentz layernorm of x -> lx
    ln_lift_k<<<ROWS, 256>>>(x, g1, b1, lx);

    // 2. Q/K/V projections + head split + lift (q stores negated time)
    dim3 gqkv(ROWS / 128, cdiv(DM, 128), 1);
    sgemm_k<false><<<gqkv, 256>>>(lx, Wq, bq, tmp, ROWS, DM, DM, DM, DM, DM, 0, 0, 0, 1.f, 0.f);
    headify_k<<<BH * SEQ / 8, 256>>>(tmp, q, -1.f);
    sgemm_k<false><<<gqkv, 256>>>(lx, Wk, bk, tmp, ROWS, DM, DM, DM, DM, DM, 0, 0, 0, 1.f, 0.f);
    headify_k<<<BH * SEQ / 8, 256>>>(tmp, k, 1.f);
    sgemm_k<false><<<gqkv, 256>>>(lx, Wv, bv, tmp, ROWS, DM, DM, DM, DM, DM, 0, 0, 0, 1.f, 0.f);
    headify_k<<<BH * SEQ / 8, 256>>>(tmp, v, 1.f);

    // 3. scores = (2 + 2 * <q',k>)/sqrt(HD)  => alpha=0.25, beta0=0.25  (batched NT)
    dim3 gsc(SEQ / 128, SEQ / 128, BH);
    sgemm_k<true><<<gsc, 256>>>(q, k, nullptr, sc, SEQ, SEQ, 65, 65, 65, SEQ,
                                (size_t)SEQ * 65, (size_t)SEQ * 65, (size_t)SEQ * SEQ,
                                0.25f, 0.25f);

    // 4. row softmax (in place)
    softmax_k<<<BH * SEQ, 256>>>(sc);

    // 5. mid = attn @ v (batched NN, K=1024, N=65)
    dim3 gmid(SEQ / 128, 1, BH);
    sgemm_k<false><<<gmid, 256>>>(sc, v, nullptr, mid, SEQ, 65, SEQ, SEQ, 65, 65,
                                  (size_t)SEQ * SEQ, (size_t)SEQ * 65, (size_t)SEQ * 65,
                                  1.f, 0.f);

    // 6. Lorentz-normalize mid, transpose heads into cat (B,N,1040)
    catnorm_k<<<BH * SEQ / 8, 256>>>(mid, cat);

    // 7. ax = lift(cat @ Wo + bo): GEMM into cols 1..1023, then time
    dim3 go(ROWS / 128, cdiv(DM - 1, 128), 1);
    sgemm_k<false><<<go, 256>>>(cat, Wo, bo, ax + 1, ROWS, DM - 1, CATW, CATW, DM - 1, DM,
                                0, 0, 0, 1.f, 0.f);
    lift_row_k<<<ROWS, 256>>>(ax, DM);

    // 8. x1 = lresnet(x, ax, w1)
    lresnet_k<<<ROWS, 256>>>(x, ax, w1, x1);

    // 9. h = Lorentz layernorm(x1)
    ln_lift_k<<<ROWS, 256>>>(x1, g2, b2, h);

    // 10. hfc = h @ Wfc + bfc
    dim3 gfc(ROWS / 128, cdiv(FF, 128), 1);
    sgemm_k<false><<<gfc, 256>>>(h, Wfc, bfc, hfc, ROWS, FF, DM, DM, FF, FF, 0, 0, 0, 1.f, 0.f);

    // 11. hg = lift(gelu(hfc))
    gelu_lift_k<<<ROWS, 256>>>(hfc, hg);

    // 12. hpj = lift(hg @ Wpj + bpj)
    dim3 gpj(ROWS / 128, cdiv(DM - 1, 128), 1);
    sgemm_k<false><<<gpj, 256>>>(hg, Wpj, bpj, hpj + 1, ROWS, DM - 1, FFL, FFL, DM - 1, DM,
                                 0, 0, 0, 1.f, 0.f);
    lift_row_k<<<ROWS, 256>>>(hpj, DM);

    // 13. out = lresnet(x1, hpj, w2)
    lresnet_k<<<ROWS, 256>>>(x1, hpj, w2, out);
}

// round 11
// speedup vs baseline: 3.0379x; 1.6727x over previous
#include <cuda_runtime.h>
#include <cuda_bf16.h>
#include <math.h>
#include <stdint.h>

#define BSZ 4
#define SEQ 1024
#define DM 1024
#define NH 16
#define HDIM 64
#define BH (BSZ*NH)            // 64
#define ROWS (BSZ*SEQ)         // 4096
#define CATW (NH*(HDIM+1))     // 1040
#define FF 4095
#define FFL 4096

// -------------------- scratch (static device allocations) --------------------
__device__ float g_lx [ROWS*DM];
__device__ float g_tmp[ROWS*DM];
__device__ float g_q  [BH*SEQ*65];
__device__ float g_k  [BH*SEQ*65];
__device__ float g_v  [BH*SEQ*65];
__device__ float g_sc [(size_t)BH*SEQ*SEQ];       // 256 MB
__device__ float g_mid[BH*SEQ*65];
__device__ float g_cat[ROWS*CATW];
__device__ float g_ax [ROWS*DM];
__device__ float g_x1 [ROWS*DM];
__device__ float g_h  [ROWS*DM];
__device__ float g_hfc[(size_t)ROWS*FF];
__device__ float g_hg [(size_t)ROWS*FFL];
__device__ float g_hpj[ROWS*DM];
// bf16 split buffers
__device__ __nv_bfloat16 g_aS[(size_t)ROWS*12288];   // 100 MB
__device__ __nv_bfloat16 g_bS[(size_t)4096*3072];    // 25 MB

__device__ __forceinline__ uint32_t smem_u32(const void* p) {
    uint32_t a;
    asm("{ .reg .u64 t; cvta.to.shared.u64 t, %1; cvt.u32.u64 %0, t; }" : "=r"(a) : "l"(p));
    return a;
}

// -------------------- reductions --------------------
__device__ __forceinline__ float warpReduceSum(float v) {
    #pragma unroll
    for (int o = 16; o; o >>= 1) v += __shfl_xor_sync(0xffffffffu, v, o);
    return v;
}
__device__ __forceinline__ float warpReduceMax(float v) {
    #pragma unroll
    for (int o = 16; o; o >>= 1) v = fmaxf(v, __shfl_xor_sync(0xffffffffu, v, o));
    return v;
}
__device__ float blockReduceSum(float v) {
    __shared__ float sbuf[32];
    __shared__ float res;
    int lane = threadIdx.x & 31, wid = threadIdx.x >> 5;
    v = warpReduceSum(v);
    if (lane == 0) sbuf[wid] = v;
    __syncthreads();
    if (wid == 0) {
        float t = (lane < ((int)blockDim.x >> 5)) ? sbuf[lane] : 0.f;
        t = warpReduceSum(t);
        if (lane == 0) res = t;
    }
    __syncthreads();
    float r = res;
    __syncthreads();
    return r;
}
__device__ float blockReduceMax(float v) {
    __shared__ float sbuf[32];
    __shared__ float res;
    int lane = threadIdx.x & 31, wid = threadIdx.x >> 5;
    v = warpReduceMax(v);
    if (lane == 0) sbuf[wid] = v;
    __syncthreads();
    if (wid == 0) {
        float t = (lane < ((int)blockDim.x >> 5)) ? sbuf[lane] : -1e30f;
        t = warpReduceMax(t);
        if (lane == 0) res = t;
    }
    __syncthreads();
    float r = res;
    __syncthreads();
    return r;
}

// -------------------- Lorentz layernorm + lift --------------------
__global__ void ln_lift_k(const float* __restrict__ x, const float* __restrict__ gamma,
                          const float* __restrict__ beta, float* __restrict__ out) {
    int row = blockIdx.x;
    const float* xs = x + (size_t)row * DM + 1;
    float* os = out + (size_t)row * DM;
    float s = 0.f;
    for (int i = threadIdx.x; i < DM - 1; i += blockDim.x) s += xs[i];
    s = blockReduceSum(s);
    float mu = s * (1.0f / (DM - 1));
    float v = 0.f;
    for (int i = threadIdx.x; i < DM - 1; i += blockDim.x) {
        float d = xs[i] - mu; v += d * d;
    }
    v = blockReduceSum(v);
    float rstd = rsqrtf(v * (1.0f / (DM - 1)) + 1e-5f);
    float sq = 0.f;
    for (int i = threadIdx.x; i < DM - 1; i += blockDim.x) {
        float y = (xs[i] - mu) * rstd * gamma[i] + beta[i];
        os[i + 1] = y;
        sq += y * y;
    }
    sq = blockReduceSum(sq);
    if (threadIdx.x == 0) os[0] = sqrtf(sq + 1.0f);
}

// -------------------- bf16 split conversions --------------------
// A'' (M x 3Kp): sections [hi | lo | hi], zero-padded cols K..Kp
__global__ void split_act_k(const float* __restrict__ A, int K, int lda,
                            __nv_bfloat16* __restrict__ out, int Kp) {
    int m = blockIdx.x;
    const float* ar = A + (size_t)m * lda;
    __nv_bfloat16* o = out + (size_t)m * 3 * Kp;
    for (int k = threadIdx.x; k < Kp; k += blockDim.x) {
        float a = (k < K) ? ar[k] : 0.f;
        __nv_bfloat16 hi = __float2bfloat16(a);
        __nv_bfloat16 lo = __float2bfloat16(a - __bfloat162float(hi));
        o[k] = hi; o[Kp + k] = lo; o[2 * Kp + k] = hi;
    }
}
// B'' (Np x 3Kp) = transpose of W(K x N): sections [hi | hi | lo], zero-padded
__global__ void split_wT_k(const float* __restrict__ W, int K, int N,
                           __nv_bfloat16* __restrict__ out, int Kp, int Np) {
    __shared__ float tile[32][33];
    int k0 = blockIdx.x * 32, n0 = blockIdx.y * 32;
    int tx = threadIdx.x & 31, ty = threadIdx.x >> 5;   // 256 threads = 32x8
    #pragma unroll
    for (int dy = 0; dy < 32; dy += 8) {
        int k = k0 + ty + dy, n = n0 + tx;
        tile[ty + dy][tx] = (k < K && n < N) ? W[(size_t)k * N + n] : 0.f;
    }
    __syncthreads();
    #pragma unroll
    for (int dy = 0; dy < 32; dy += 8) {
        int n = n0 + ty + dy, k = k0 + tx;
        if (n < Np && k < Kp) {
            float w = tile[tx][ty + dy];
            __nv_bfloat16 hi = __float2bfloat16(w);
            __nv_bfloat16 lo = __float2bfloat16(w - __bfloat162float(hi));
            __nv_bfloat16* o = out + (size_t)n * 3 * Kp;
            o[k] = hi; o[Kp + k] = hi; o[2 * Kp + k] = lo;
        }
    }
}

// -------------------- mma.sync bf16 GEMM: C[M,N] = A''(M x K3) @ B''(N x K3)^T + bias ------
// 128x128 CTA tile, 8 warps (64x32 warp tile), K-tile 32 bf16, 80B padded smem rows.
#define KT 32
#define RS 40   // row stride in bf16 elems (80 bytes, conflict-free ldmatrix)

__global__ void __launch_bounds__(256)
mma_gemm_k(const __nv_bfloat16* __restrict__ A, const __nv_bfloat16* __restrict__ B,
           const float* __restrict__ bias, float* __restrict__ C,
           int N, int ldc, int K3) {
    __shared__ __nv_bfloat16 smA[2][128 * RS];
    __shared__ __nv_bfloat16 smB[2][128 * RS];
    int tid = threadIdx.x, lane = tid & 31, wid = tid >> 5;
    int rb = blockIdx.x * 128, cb = blockIdx.y * 128;
    int wm = wid & 1, wn = wid >> 1;            // 2 x 4 warp grid
    float acc[4][4][4];
    #pragma unroll
    for (int i = 0; i < 4; i++)
        #pragma unroll
        for (int j = 0; j < 4; j++)
            #pragma unroll
            for (int t = 0; t < 4; t++) acc[i][j][t] = 0.f;

    int nkt = K3 / KT;
    uint4 pa[2], pb[2];
    // prefetch K-tile 0
    #pragma unroll
    for (int t = 0; t < 2; t++) {
        int idx = tid + t * 256;
        int row = idx >> 2, c4 = idx & 3;
        pa[t] = *(const uint4*)(A + (size_t)(rb + row) * K3 + c4 * 8);
        pb[t] = *(const uint4*)(B + (size_t)(cb + row) * K3 + c4 * 8);
    }
    #pragma unroll
    for (int t = 0; t < 2; t++) {
        int idx = tid + t * 256;
        int row = idx >> 2, c4 = idx & 3;
        *(uint4*)(&smA[0][row * RS + c4 * 8]) = pa[t];
        *(uint4*)(&smB[0][row * RS + c4 * 8]) = pb[t];
    }
    __syncthreads();

    uint32_t baseA = smem_u32(smA);
    uint32_t baseB = smem_u32(smB);

    #pragma unroll 1
    for (int kt = 0; kt < nkt; kt++) {
        int cur = kt & 1, nxt = cur ^ 1;
        bool more = (kt + 1 < nkt);
        if (more) {
            int k0 = (kt + 1) * KT;
            #pragma unroll
            for (int t = 0; t < 2; t++) {
                int idx = tid + t * 256;
                int row = idx >> 2, c4 = idx & 3;
                pa[t] = *(const uint4*)(A + (size_t)(rb + row) * K3 + k0 + c4 * 8);
                pb[t] = *(const uint4*)(B + (size_t)(cb + row) * K3 + k0 + c4 * 8);
            }
        }
        uint32_t sA = baseA + cur * (128 * RS * 2);
        uint32_t sB = baseB + cur * (128 * RS * 2);
        #pragma unroll
        for (int ks = 0; ks < 2; ks++) {
            uint32_t af[4][4], bf[4][2];
            #pragma unroll
            for (int i = 0; i < 4; i++) {
                int row = wm * 64 + i * 16 + (lane & 15);
                uint32_t addr = sA + row * 80 + ks * 32 + ((lane >> 4) & 1) * 16;
                asm volatile("ldmatrix.sync.aligned.m8n8.x4.shared.b16 {%0,%1,%2,%3}, [%4];"
                             : "=r"(af[i][0]), "=r"(af[i][1]), "=r"(af[i][2]), "=r"(af[i][3])
                             : "r"(addr));
            }
            #pragma unroll
            for (int j = 0; j < 4; j++) {
                int l = lane & 15;
                int nrow = wn * 32 + j * 8 + (l & 7);
                uint32_t addr = sB + nrow * 80 + ks * 32 + ((l >> 3) & 1) * 16;
                asm volatile("ldmatrix.sync.aligned.m8n8.x2.shared.b16 {%0,%1}, [%2];"
                             : "=r"(bf[j][0]), "=r"(bf[j][1]) : "r"(addr));
            }
            #pragma unroll
            for (int i = 0; i < 4; i++)
                #pragma unroll
                for (int j = 0; j < 4; j++)
                    asm volatile(
                        "mma.sync.aligned.m16n8k16.row.col.f32.bf16.bf16.f32 "
                        "{%0,%1,%2,%3}, {%4,%5,%6,%7}, {%8,%9}, {%0,%1,%2,%3};"
                        : "+f"(acc[i][j][0]), "+f"(acc[i][j][1]),
                          "+f"(acc[i][j][2]), "+f"(acc[i][j][3])
                        : "r"(af[i][0]), "r"(af[i][1]), "r"(af[i][2]), "r"(af[i][3]),
                          "r"(bf[j][0]), "r"(bf[j][1]));
        }
        if (more) {
            #pragma unroll
            for (int t = 0; t < 2; t++) {
                int idx = tid + t * 256;
                int row = idx >> 2, c4 = idx & 3;
                *(uint4*)(&smA[nxt][row * RS + c4 * 8]) = pa[t];
                *(uint4*)(&smB[nxt][row * RS + c4 * 8]) = pb[t];
            }
        }
        __syncthreads();
    }

    // epilogue: acc layout m16n8: lane>>2 = row in 8-group, lane&3 -> col pair
    #pragma unroll
    for (int i = 0; i < 4; i++) {
        int r0 = rb + wm * 64 + i * 16 + (lane >> 2);
        #pragma unroll
        for (int j = 0; j < 4; j++) {
            int c0 = cb + wn * 32 + j * 8 + (lane & 3) * 2;
            float* cp0 = C + (size_t)r0 * ldc;
            float* cp1 = C + (size_t)(r0 + 8) * ldc;
            if (c0 < N) {
                float bv = bias ? bias[c0] : 0.f;
                cp0[c0] = acc[i][j][0] + bv;
                cp1[c0] = acc[i][j][2] + bv;
            }
            if (c0 + 1 < N) {
                float bv = bias ? bias[c0 + 1] : 0.f;
                cp0[c0 + 1] = acc[i][j][1] + bv;
                cp1[c0 + 1] = acc[i][j][3] + bv;
            }
        }
    }
}

// -------------------- FFMA SGEMM (attention: scores + AV) --------------------
template <bool TRANS_B>
__global__ void __launch_bounds__(256, 2)
sgemm_k(const float* __restrict__ A, const float* __restrict__ Bm,
        const float* __restrict__ bias, float* __restrict__ C,
        int M, int N, int K, int lda, int ldb, int ldc,
        size_t sA, size_t sB, size_t sC, float alpha, float beta0) {
    __shared__ float As[2][16][132];
    __shared__ float Bs[2][16][132];
    A  += blockIdx.z * sA;
    Bm += blockIdx.z * sB;
    C  += blockIdx.z * sC;
    int rb = blockIdx.x * 128, cb = blockIdx.y * 128;
    int tid = threadIdx.x;
    int tx = tid & 15, ty = tid >> 4;
    float acc[8][8] = {};
    int nkt = (K + 15) >> 4;
    float ra[8], rbv[8];
    {
        int k0 = 0;
        #pragma unroll
        for (int t = 0; t < 8; t++) {
            int idx = tid + t * 256;
            int r = idx >> 4, c = idx & 15;
            int gr = rb + r, gk = k0 + c;
            ra[t] = (gr < M && gk < K) ? A[(size_t)gr * lda + gk] : 0.f;
        }
        #pragma unroll
        for (int t = 0; t < 8; t++) {
            int idx = tid + t * 256;
            if (TRANS_B) {
                int n = idx >> 4, c = idx & 15;
                int gn = cb + n, gk = k0 + c;
                rbv[t] = (gn < N && gk < K) ? Bm[(size_t)gn * ldb + gk] : 0.f;
            } else {
                int c = idx >> 7, n = idx & 127;
                int gk = k0 + c, gn = cb + n;
                rbv[t] = (gk < K && gn < N) ? Bm[(size_t)gk * ldb + gn] : 0.f;
            }
        }
    }
    #pragma unroll
    for (int t = 0; t < 8; t++) {
        int idx = tid + t * 256;
        As[0][idx & 15][idx >> 4] = ra[t];
    }
    #pragma unroll
    for (int t = 0; t < 8; t++) {
        int idx = tid + t * 256;
        if (TRANS_B) Bs[0][idx & 15][idx >> 4] = rbv[t];
        else         Bs[0][idx >> 7][idx & 127] = rbv[t];
    }
    __syncthreads();
    #pragma unroll 1
    for (int kt = 0; kt < nkt; kt++) {
        int cur = kt & 1, nxt = cur ^ 1;
        bool more = (kt + 1 < nkt);
        if (more) {
            int k0 = (kt + 1) << 4;
            #pragma unroll
            for (int t = 0; t < 8; t++) {
                int idx = tid + t * 256;
                int r = idx >> 4, c = idx & 15;
                int gr = rb + r, gk = k0 + c;
                ra[t] = (gr < M && gk < K) ? A[(size_t)gr * lda + gk] : 0.f;
            }
            #pragma unroll
            for (int t = 0; t < 8; t++) {
                int idx = tid + t * 256;
                if (TRANS_B) {
                    int n = idx >> 4, c = idx & 15;
                    int gn = cb + n, gk = k0 + c;
                    rbv[t] = (gn < N && gk < K) ? Bm[(size_t)gn * ldb + gk] : 0.f;
                } else {
                    int c = idx >> 7, n = idx & 127;
                    int gk = k0 + c, gn = cb + n;
                    rbv[t] = (gk < K && gn < N) ? Bm[(size_t)gk * ldb + gn] : 0.f;
                }
            }
        }
        #pragma unroll
        for (int k = 0; k < 16; k++) {
            float4 a0 = *(const float4*)&As[cur][k][ty * 8];
            float4 a1 = *(const float4*)&As[cur][k][ty * 8 + 4];
            float4 b0 = *(const float4*)&Bs[cur][k][tx * 8];
            float4 b1 = *(const float4*)&Bs[cur][k][tx * 8 + 4];
            float a[8] = {a0.x, a0.y, a0.z, a0.w, a1.x, a1.y, a1.z, a1.w};
            float b[8] = {b0.x, b0.y, b0.z, b0.w, b1.x, b1.y, b1.z, b1.w};
            #pragma unroll
            for (int i = 0; i < 8; i++)
                #pragma unroll
                for (int j = 0; j < 8; j++)
                    acc[i][j] = fmaf(a[i], b[j], acc[i][j]);
        }
        if (more) {
            #pragma unroll
            for (int t = 0; t < 8; t++) {
                int idx = tid + t * 256;
                As[nxt][idx & 15][idx >> 4] = ra[t];
            }
            #pragma unroll
            for (int t = 0; t < 8; t++) {
                int idx = tid + t * 256;
                if (TRANS_B) Bs[nxt][idx & 15][idx >> 4] = rbv[t];
                else         Bs[nxt][idx >> 7][idx & 127] = rbv[t];
            }
        }
        __syncthreads();
    }
    #pragma unroll
    for (int i = 0; i < 8; i++) {
        int gr = rb + ty * 8 + i;
        if (gr >= M) continue;
        #pragma unroll
        for (int j = 0; j < 8; j++) {
            int gn = cb + tx * 8 + j;
            if (gn >= N) continue;
            float bv = bias ? bias[gn] : 0.f;
            C[(size_t)gr * ldc + gn] = alpha * acc[i][j] + beta0 + bv;
        }
    }
}

// -------------------- reshape to heads + lift --------------------
__global__ void headify_k(const float* __restrict__ t, float* __restrict__ dst, float tsgn) {
    int gw = (blockIdx.x * blockDim.x + threadIdx.x) >> 5;
    int lane = threadIdx.x & 31;
    if (gw >= BH * SEQ) return;
    int n = gw & (SEQ - 1);
    int bh = gw >> 10;
    int h = bh & (NH - 1), b = bh >> 4;
    const float* src = t + ((size_t)(b * SEQ + n)) * DM + h * HDIM;
    float v0 = src[lane], v1 = src[32 + lane];
    float s = v0 * v0 + v1 * v1;
    #pragma unroll
    for (int o = 16; o; o >>= 1) s += __shfl_xor_sync(0xffffffffu, s, o);
    float tv = sqrtf(s + 1.0f);
    float* d = dst + (size_t)gw * 65;
    if (lane == 0) d[0] = tsgn * tv;
    d[1 + lane] = v0;
    d[33 + lane] = v1;
}

// -------------------- softmax --------------------
__global__ void softmax_k(float* __restrict__ sc) {
    size_t row = blockIdx.x;
    float* r = sc + row * SEQ;
    float v[4];
    float m = -1e30f;
    #pragma unroll
    for (int t = 0; t < 4; t++) { v[t] = r[threadIdx.x + t * 256]; m = fmaxf(m, v[t]); }
    m = blockReduceMax(m);
    float s = 0.f;
    #pragma unroll
    for (int t = 0; t < 4; t++) { v[t] = expf(v[t] - m); s += v[t]; }
    s = blockReduceSum(s);
    float inv = 1.0f / s;
    #pragma unroll
    for (int t = 0; t < 4; t++) r[threadIdx.x + t * 256] = v[t] * inv;
}

// -------------------- mid normalize + concat --------------------
__global__ void catnorm_k(const float* __restrict__ mid, float* __restrict__ cat) {
    int gw = (blockIdx.x * blockDim.x + threadIdx.x) >> 5;
    int lane = threadIdx.x & 31;
    if (gw >= BH * SEQ) return;
    int n = gw & (SEQ - 1);
    int bh = gw >> 10;
    int h = bh & (NH - 1), b = bh >> 4;
    const float* src = mid + (size_t)gw * 65;
    float t0 = src[0];
    float v0 = src[1 + lane], v1 = src[33 + lane];
    float s = v0 * v0 + v1 * v1;
    #pragma unroll
    for (int o = 16; o; o >>= 1) s += __shfl_xor_sync(0xffffffffu, s, o);
    float nl = t0 * t0 - s;
    float inv = rsqrtf(fmaxf(nl, 1e-8f));
    float* d = cat + ((size_t)(b * SEQ + n)) * CATW + h * 65;
    if (lane == 0) d[0] = t0 * inv;
    d[1 + lane] = v0 * inv;
    d[33 + lane] = v1 * inv;
}

// -------------------- fill time component --------------------
__global__ void lift_row_k(float* __restrict__ m, int C) {
    int row = blockIdx.x;
    float* r = m + (size_t)row * C;
    float s = 0.f;
    for (int i = 1 + threadIdx.x; i < C; i += blockDim.x) { float v = r[i]; s += v * v; }
    s = blockReduceSum(s);
    if (threadIdx.x == 0) r[0] = sqrtf(s + 1.0f);
}

// -------------------- Lorentz residual --------------------
__global__ void lresnet_k(const float* __restrict__ x, const float* __restrict__ y,
                          const float* __restrict__ wp, float* __restrict__ out) {
    int row = blockIdx.x;
    const float* xr = x + (size_t)row * DM;
    const float* yr = y + (size_t)row * DM;
    float w = *wp;
    float z[4];
    float s = 0.f;
    #pragma unroll
    for (int t = 0; t < 4; t++) {
        int i = threadIdx.x + t * 256;
        float zz = xr[i] + w * yr[i];
        z[t] = zz;
        s += (i == 0) ? zz * zz : -(zz * zz);
    }
    s = blockReduceSum(s);
    float inv = rsqrtf(fmaxf(s, 1e-8f));
    float* o = out + (size_t)row * DM;
    #pragma unroll
    for (int t = 0; t < 4; t++) o[threadIdx.x + t * 256] = z[t] * inv;
}

// -------------------- exact gelu + lift --------------------
__global__ void gelu_lift_k(const float* __restrict__ in, float* __restrict__ out) {
    int row = blockIdx.x;
    const float* ir = in + (size_t)row * FF;
    float* orow = out + (size_t)row * FFL;
    float s = 0.f;
    for (int i = threadIdx.x; i < FF; i += blockDim.x) {
        float v = ir[i];
        float g = 0.5f * v * (1.0f + erff(v * 0.70710678118654752f));
        orow[1 + i] = g;
        s += g * g;
    }
    s = blockReduceSum(s);
    if (threadIdx.x == 0) orow[0] = sqrtf(s + 1.0f);
}

// -------------------- host --------------------
static inline int cdiv(int a, int b) { return (a + b - 1) / b; }

extern "C" void kernel_launch(void* const* d_in, const int* in_sizes, int n_in,
                              void* d_out, int out_size) {
    const float* x   = (const float*)d_in[0];
    const float* g1  = (const float*)d_in[1];
    const float* b1  = (const float*)d_in[2];
    const float* Wq  = (const float*)d_in[3];
    const float* bq  = (const float*)d_in[4];
    const float* Wk  = (const float*)d_in[5];
    const float* bk  = (const float*)d_in[6];
    const float* Wv  = (const float*)d_in[7];
    const float* bv  = (const float*)d_in[8];
    const float* Wo  = (const float*)d_in[9];
    const float* bo  = (const float*)d_in[10];
    const float* g2  = (const float*)d_in[11];
    const float* b2  = (const float*)d_in[12];
    const float* Wfc = (const float*)d_in[13];
    const float* bfc = (const float*)d_in[14];
    const float* Wpj = (const float*)d_in[15];
    const float* bpj = (const float*)d_in[16];
    const float* w1  = (const float*)d_in[17];
    const float* w2  = (const float*)d_in[18];
    float* out = (float*)d_out;

    float *lx, *tmp, *q, *k, *v, *sc, *mid, *cat, *ax, *x1, *h, *hfc, *hg, *hpj;
    __nv_bfloat16 *aS, *bS;
    cudaGetSymbolAddress((void**)&lx,  g_lx);
    cudaGetSymbolAddress((void**)&tmp, g_tmp);
    cudaGetSymbolAddress((void**)&q,   g_q);
    cudaGetSymbolAddress((void**)&k,   g_k);
    cudaGetSymbolAddress((void**)&v,   g_v);
    cudaGetSymbolAddress((void**)&sc,  g_sc);
    cudaGetSymbolAddress((void**)&mid, g_mid);
    cudaGetSymbolAddress((void**)&cat, g_cat);
    cudaGetSymbolAddress((void**)&ax,  g_ax);
    cudaGetSymbolAddress((void**)&x1,  g_x1);
    cudaGetSymbolAddress((void**)&h,   g_h);
    cudaGetSymbolAddress((void**)&hfc, g_hfc);
    cudaGetSymbolAddress((void**)&hg,  g_hg);
    cudaGetSymbolAddress((void**)&hpj, g_hpj);
    cudaGetSymbolAddress((void**)&aS,  g_aS);
    cudaGetSymbolAddress((void**)&bS,  g_bS);

    // 1. Lorentz layernorm of x -> lx
    ln_lift_k<<<ROWS, 256>>>(x, g1, b1, lx);

    // 2. QKV via mma.sync bf16x3
    split_act_k<<<ROWS, 256>>>(lx, DM, DM, aS, 1024);          // 3Kp = 3072
    dim3 gq(ROWS / 128, 1024 / 128);
    const float* Ws[3]  = {Wq, Wk, Wv};
    const float* bs_[3] = {bq, bk, bv};
    float tsg[3] = {-1.f, 1.f, 1.f};
    float* dsts[3] = {q, k, v};
    for (int i = 0; i < 3; i++) {
        split_wT_k<<<dim3(cdiv(1024, 32), cdiv(1024, 32)), 256>>>(Ws[i], DM, DM, bS, 1024, 1024);
        mma_gemm_k<<<gq, 256>>>(aS, bS, bs_[i], tmp, DM, DM, 3072);
        headify_k<<<BH * SEQ / 8, 256>>>(tmp, dsts[i], tsg[i]);
    }

    // 3. scores = (2 + 2 <q',k>)/8 (FFMA batched NT)
    dim3 gsc(SEQ / 128, SEQ / 128, BH);
    sgemm_k<true><<<gsc, 256>>>(q, k, nullptr, sc, SEQ, SEQ, 65, 65, 65, SEQ,
                                (size_t)SEQ * 65, (size_t)SEQ * 65, (size_t)SEQ * SEQ,
                                0.25f, 0.25f);
    // 4. softmax
    softmax_k<<<BH * SEQ, 256>>>(sc);
    // 5. mid = attn @ v (FFMA batched NN)
    dim3 gmid(SEQ / 128, 1, BH);
    sgemm_k<false><<<gmid, 256>>>(sc, v, nullptr, mid, SEQ, 65, SEQ, SEQ, 65, 65,
                                  (size_t)SEQ * SEQ, (size_t)SEQ * 65, (size_t)SEQ * 65,
                                  1.f, 0.f);
    // 6. normalize + concat heads
    catnorm_k<<<BH * SEQ / 8, 256>>>(mid, cat);

    // 7. ax = lift(cat @ Wo + bo) : K=1040 -> Kp=1088, N=1023
    split_act_k<<<ROWS, 256>>>(cat, CATW, CATW, aS, 1088);     // 3Kp = 3264
    split_wT_k<<<dim3(cdiv(1088, 32), cdiv(1024, 32)), 256>>>(Wo, CATW, DM - 1, bS, 1088, 1024);
    mma_gemm_k<<<dim3(ROWS / 128, 8), 256>>>(aS, bS, bo, ax + 1, DM - 1, DM, 3264);
    lift_row_k<<<ROWS, 256>>>(ax, DM);

    // 8. x1 = lresnet(x, ax, w1)
    lresnet_k<<<ROWS, 256>>>(x, ax, w1, x1);
    // 9. h = layernorm(x1)
    ln_lift_k<<<ROWS, 256>>>(x1, g2, b2, h);

    // 10. hfc = h @ Wfc + bfc : K=1024, N=4095
    split_act_k<<<ROWS, 256>>>(h, DM, DM, aS, 1024);           // 3Kp = 3072
    split_wT_k<<<dim3(cdiv(1024, 32), cdiv(4096, 32)), 256>>>(Wfc, DM, FF, bS, 1024, 4096);
    mma_gemm_k<<<dim3(ROWS / 128, 32), 256>>>(aS, bS, bfc, hfc, FF, FF, 3072);

    // 11. hg = lift(gelu(hfc))
    gelu_lift_k<<<ROWS, 256>>>(hfc, hg);

    // 12. hpj = lift(hg @ Wpj + bpj) : K=4096, N=1023
    split_act_k<<<ROWS, 256>>>(hg, FFL, FFL, aS, 4096);        // 3Kp = 12288
    split_wT_k<<<dim3(cdiv(4096, 32), cdiv(1024, 32)), 256>>>(Wpj, FFL, DM - 1, bS, 4096, 1024);
    mma_gemm_k<<<dim3(ROWS / 128, 8), 256>>>(aS, bS, bpj, hpj + 1, DM - 1, DM, 12288);
    lift_row_k<<<ROWS, 256>>>(hpj, DM);

    // 13. out = lresnet(x1, hpj, w2)
    lresnet_k<<<ROWS, 256>>>(x1, hpj, w2, out);
}